// round 13
// baseline (speedup 1.0000x reference)
#include <cuda_runtime.h>
#include <cuda_fp16.h>
#include <math.h>
#include <stdint.h>

#define BS 128
#define SL 512
#define HD 1024
#define DD 512
#define M_TOTAL (BS * SL)          // 65536
#define KPHYS 2048                 // [hi | lo] physical K (halves)
#define NEG_FILL -1000000.0f

#define BM 128
#define BN 128
#define NB (DD / BN)               // 4 n-blocks
#define BK 32                      // fp32 cols per chunk (32 hi + 32 lo halves)
#define NCHUNK_P 32                // 1024 / 32
#define STAGES 3
#define T_BYTES (128 * BK * 2)     // 8192
#define A_HI 0
#define A_LO T_BYTES
#define B_HI (2 * T_BYTES)
#define B_LO (3 * T_BYTES)
#define STAGE_BYTES (4 * T_BYTES)  // 32768
#define OFF_RED  (STAGES * STAGE_BYTES)        // 98304, 1KB
#define OFF_BQ   (OFF_RED + 1024)              // 99328, 512B
#define OFF_VQ   (OFF_BQ + 512)                // 99840, 512B
#define SMEM_GEMM (OFF_VQ + 512)               // 100352 -> 2 CTAs/SM
#define MAX_TILES (M_TOTAL / BM)   // 512

// 64-byte row swizzle: 4 x 16B blocks per row, phase by (row>>1)&3
#define SW64(r, j) ((r) * 64 + ((((j) ^ (((r) >> 1) & 3))) << 4))

// ---------------- device scratch (no allocations allowed) -------------------
__device__ __half g_A[(size_t)M_TOTAL * KPHYS];   // 268 MB (upper bound)
__device__ __half g_B[(size_t)DD * KPHYS];        // 2 MB
__device__ float  g_spart[M_TOTAL * NB];
__device__ int    g_cnt[BS];
__device__ int    g_boff[BS];
__device__ int    g_total;
__device__ int    g_src[M_TOTAL];

// ---------------- helpers ----------------------------------------------------
__device__ __forceinline__ uint32_t smem_u32(const void* p) {
    uint32_t a;
    asm("{ .reg .u64 t; cvta.to.shared.u64 t, %1; cvt.u32.u64 %0, t; }" : "=r"(a) : "l"(p));
    return a;
}
#define CP16(dst, src) \
    asm volatile("cp.async.cg.shared.global [%0], [%1], 16;" :: "r"(dst), "l"(src) : "memory")
#define CP_COMMIT() asm volatile("cp.async.commit_group;" ::: "memory")
#define CP_WAIT1()  asm volatile("cp.async.wait_group 1;" ::: "memory")
#define CP_WAIT0()  asm volatile("cp.async.wait_group 0;" ::: "memory")

__device__ __forceinline__ void ldsm_x4(uint32_t addr, uint32_t& r0, uint32_t& r1,
                                        uint32_t& r2, uint32_t& r3) {
    asm volatile("ldmatrix.sync.aligned.m8n8.x4.shared.b16 {%0,%1,%2,%3}, [%4];"
                 : "=r"(r0), "=r"(r1), "=r"(r2), "=r"(r3) : "r"(addr));
}
__device__ __forceinline__ void mma16816(float* c, const uint32_t* a,
                                         uint32_t b0, uint32_t b1) {
    asm volatile(
        "mma.sync.aligned.m16n8k16.row.col.f32.f16.f16.f32 "
        "{%0,%1,%2,%3},{%4,%5,%6,%7},{%8,%9},{%0,%1,%2,%3};"
        : "+f"(c[0]), "+f"(c[1]), "+f"(c[2]), "+f"(c[3])
        : "r"(a[0]), "r"(a[1]), "r"(a[2]), "r"(a[3]), "r"(b0), "r"(b1));
}

// ---------------------------------------------------------------------------
// Map (count fused in): block b computes its offset by summing keeps of all
// earlier batches (mask is L2-resident, 256 KB), then ballot/popc scan.
// ---------------------------------------------------------------------------
__global__ __launch_bounds__(512) void map_kernel(const int* __restrict__ mask)
{
    __shared__ int wsum[16];
    __shared__ int osum[16];
    __shared__ int s_off;
    const int b = blockIdx.x, s = threadIdx.x;
    const int warp = s >> 5, lane = s & 31;

    // offset = number of keeps in batches [0, b)
    int off = 0;
    const int lim = b * SL;
    for (int idx = s; idx < lim; idx += 512) off += (mask[idx] == 0);
#pragma unroll
    for (int d = 16; d > 0; d >>= 1) off += __shfl_xor_sync(0xFFFFFFFF, off, d);
    if (lane == 0) osum[warp] = off;
    __syncthreads();
    if (warp == 0) {
        int v = (lane < 16) ? osum[lane] : 0;
#pragma unroll
        for (int d = 16; d > 0; d >>= 1) v += __shfl_xor_sync(0xFFFFFFFF, v, d);
        if (lane == 0) s_off = v;
    }

    // within-batch exclusive scan of keeps
    const int m = b * SL + s;
    const int keep = (mask[m] == 0);
    const uint32_t bal = __ballot_sync(0xFFFFFFFF, keep);
    const uint32_t lmask_lt = (lane == 0) ? 0u : (0xFFFFFFFFu >> (32 - lane));
    const int excl_in_warp = __popc(bal & lmask_lt);
    if (lane == 0) wsum[warp] = __popc(bal);
    __syncthreads();

    if (warp == 0 && lane < 16) {
        int v = wsum[lane];
#pragma unroll
        for (int d = 1; d < 16; d <<= 1) {
            int t = __shfl_up_sync(0x0000FFFF, v, d, 16);
            if (lane >= d) v += t;
        }
        wsum[lane] = v;   // inclusive
    }
    __syncthreads();

    const int warp_excl = (warp == 0) ? 0 : wsum[warp - 1];
    const int r = s_off + warp_excl + excl_in_warp;
    if (keep) g_src[r] = m;
    if (s == SL - 1) {
        g_boff[b] = s_off;
        g_cnt[b]  = (r + keep) - s_off;
        if (b == BS - 1) g_total = r + keep;
    }
}

// ---------------------------------------------------------------------------
// Gather + fp32 -> [hi | lo] fp16 split; first 512 blocks also convert Wq.
// ---------------------------------------------------------------------------
__global__ __launch_bounds__(256) void conv_kernel(const float* __restrict__ x,
                                                   const float* __restrict__ Wq)
{
    const int t = threadIdx.x;

    if (blockIdx.x < 512) {
        size_t g = (size_t)blockIdx.x * 256 + t;
        size_t n = g >> 8;
        int kq = (int)(g & 255) << 2;
        float4 v = *reinterpret_cast<const float4*>(Wq + n * HD + kq);

        __half h0 = __float2half_rn(v.x), h1 = __float2half_rn(v.y);
        __half h2 = __float2half_rn(v.z), h3 = __float2half_rn(v.w);
        __half l0 = __float2half_rn(v.x - __half2float(h0));
        __half l1 = __float2half_rn(v.y - __half2float(h1));
        __half l2 = __float2half_rn(v.z - __half2float(h2));
        __half l3 = __float2half_rn(v.w - __half2float(h3));

        __half2* ph = reinterpret_cast<__half2*>(g_B + n * KPHYS + kq);
        __half2* pl = reinterpret_cast<__half2*>(g_B + n * KPHYS + 1024 + kq);
        ph[0] = __halves2half2(h0, h1); ph[1] = __halves2half2(h2, h3);
        pl[0] = __halves2half2(l0, l1); pl[1] = __halves2half2(l2, l3);
    }

    const int total = g_total;
    for (int r = blockIdx.x; r < total; r += 16384) {
        const float* src = x + (size_t)g_src[r] * HD + (t << 2);
        const float4 v = *reinterpret_cast<const float4*>(src);

        __half h0 = __float2half_rn(v.x), h1 = __float2half_rn(v.y);
        __half h2 = __float2half_rn(v.z), h3 = __float2half_rn(v.w);
        __half l0 = __float2half_rn(v.x - __half2float(h0));
        __half l1 = __float2half_rn(v.y - __half2float(h1));
        __half l2 = __float2half_rn(v.z - __half2float(h2));
        __half l3 = __float2half_rn(v.w - __half2float(h3));

        __half2* ph = reinterpret_cast<__half2*>(g_A + (size_t)r * KPHYS + (t << 2));
        __half2* pl = reinterpret_cast<__half2*>(g_A + (size_t)r * KPHYS + 1024 + (t << 2));
        ph[0] = __halves2half2(h0, h1); ph[1] = __halves2half2(h2, h3);
        pl[0] = __halves2half2(l0, l1); pl[1] = __halves2half2(l2, l3);
    }
}

// ---------------------------------------------------------------------------
// GEMM: CTA tile 128x128, 256 threads = 8 warps (4m x 2n), warp tile 32x64,
// BK=32, 2 CTAs/SM, ONE barrier per chunk, bq/vq staged in smem.
// ---------------------------------------------------------------------------
__device__ __forceinline__ void load_chunk(int chunk, uint32_t stage, int m0, int n0,
                                           int tid)
{
    const int k = chunk * BK;
    const __half* ah = g_A + (size_t)m0 * KPHYS + k;
    const __half* bh = g_B + (size_t)n0 * KPHYS + k;

#pragma unroll
    for (int u = 0; u < 2; u++) {
        int idx = tid + u * 256;
        int r = idx >> 2, j = idx & 3;
        uint32_t sw = SW64(r, j);
        const size_t go = (size_t)r * KPHYS + j * 8;
        CP16(stage + A_HI + sw, ah + go);
        CP16(stage + A_LO + sw, ah + 1024 + go);
        CP16(stage + B_HI + sw, bh + go);
        CP16(stage + B_LO + sw, bh + 1024 + go);
    }
    CP_COMMIT();
}

__global__ __launch_bounds__(256, 2) void gemm_kernel(const float* __restrict__ bq,
                                                      const float* __restrict__ vq)
{
    const int ntiles = (g_total + BM - 1) >> 7;
    if ((int)blockIdx.y >= ntiles) return;

    extern __shared__ char smem[];
    const uint32_t sb = smem_u32(smem);
    const int tid = threadIdx.x;
    const int wid = tid >> 5, lane = tid & 31;
    const int wm = wid & 3, wn = wid >> 2;
    const int m0 = blockIdx.y * BM;
    const int nb = blockIdx.x;
    const int n0 = nb * BN;

    float* s_bq = reinterpret_cast<float*>(smem + OFF_BQ);
    float* s_vq = reinterpret_cast<float*>(smem + OFF_VQ);
    if (tid < 128) { s_bq[tid] = bq[n0 + tid]; s_vq[tid] = vq[n0 + tid]; }

    float acc[2][8][4];
#pragma unroll
    for (int i = 0; i < 2; i++)
#pragma unroll
        for (int j = 0; j < 8; j++)
#pragma unroll
            for (int k = 0; k < 4; k++) acc[i][j][k] = 0.0f;

    const int arow = wm * 32 + (lane & 15);
    const int aj   = (lane >> 4);
    const int brow = wn * 64 + (lane & 7) + ((lane >> 4) & 1) * 8;
    const int bj   = ((lane >> 3) & 1);

    load_chunk(0, sb + 0 * STAGE_BYTES, m0, n0, tid);
    load_chunk(1, sb + 1 * STAGE_BYTES, m0, n0, tid);

#pragma unroll 1
    for (int i = 0; i < NCHUNK_P; i++) {
        if (i == NCHUNK_P - 1) { CP_WAIT0(); } else { CP_WAIT1(); }
        __syncthreads();     // chunk i resident; all warps done with chunk i-1

        if (i + 2 < NCHUNK_P)
            load_chunk(i + 2, sb + ((i + 2) % 3) * STAGE_BYTES, m0, n0, tid);

        const uint32_t st = sb + (i % 3) * STAGE_BYTES;

#pragma unroll
        for (int kk = 0; kk < 2; kk++) {
            uint32_t ah0[4], ah1[4], al0[4], al1[4];
            const int j = kk * 2 + aj;
            {
                int r = arow;
                uint32_t sw = SW64(r, j);
                ldsm_x4(st + A_HI + sw, ah0[0], ah0[1], ah0[2], ah0[3]);
                ldsm_x4(st + A_LO + sw, al0[0], al0[1], al0[2], al0[3]);
                r = arow + 16;
                sw = SW64(r, j);
                ldsm_x4(st + A_HI + sw, ah1[0], ah1[1], ah1[2], ah1[3]);
                ldsm_x4(st + A_LO + sw, al1[0], al1[1], al1[2], al1[3]);
            }
#pragma unroll
            for (int nt2 = 0; nt2 < 4; nt2++) {
                const int r = brow + nt2 * 16;
                const int jb = kk * 2 + bj;
                const uint32_t sw = SW64(r, jb);
                uint32_t h0, h1, h2, h3, l0, l1, l2, l3;
                ldsm_x4(st + B_HI + sw, h0, h1, h2, h3);
                ldsm_x4(st + B_LO + sw, l0, l1, l2, l3);
                mma16816(acc[0][2 * nt2],     ah0, h0, h1);
                mma16816(acc[0][2 * nt2 + 1], ah0, h2, h3);
                mma16816(acc[1][2 * nt2],     ah1, h0, h1);
                mma16816(acc[1][2 * nt2 + 1], ah1, h2, h3);
                mma16816(acc[0][2 * nt2],     al0, h0, h1);
                mma16816(acc[0][2 * nt2 + 1], al0, h2, h3);
                mma16816(acc[1][2 * nt2],     al1, h0, h1);
                mma16816(acc[1][2 * nt2 + 1], al1, h2, h3);
                mma16816(acc[0][2 * nt2],     ah0, l0, l1);
                mma16816(acc[0][2 * nt2 + 1], ah0, l2, l3);
                mma16816(acc[1][2 * nt2],     ah1, l0, l1);
                mma16816(acc[1][2 * nt2 + 1], ah1, l2, l3);
            }
        }
    }

    // ---- epilogue: per-row sum of vq[n]*tanh(D+bq[n]) over this 128-n block ----
    float* sred = reinterpret_cast<float*>(smem + OFF_RED);
    const int g = lane >> 2, tig = lane & 3;

    float rs[2][2] = {{0.f, 0.f}, {0.f, 0.f}};
#pragma unroll
    for (int mt = 0; mt < 2; mt++) {
#pragma unroll
        for (int nt = 0; nt < 8; nt++) {
            const int nl = wn * 64 + nt * 8 + 2 * tig;
            const float b0 = s_bq[nl], b1 = s_bq[nl + 1];
            const float v0 = s_vq[nl], v1 = s_vq[nl + 1];
            rs[mt][0] += v0 * tanhf(acc[mt][nt][0] + b0) + v1 * tanhf(acc[mt][nt][1] + b1);
            rs[mt][1] += v0 * tanhf(acc[mt][nt][2] + b0) + v1 * tanhf(acc[mt][nt][3] + b1);
        }
    }
#pragma unroll
    for (int d = 1; d <= 2; d <<= 1) {
#pragma unroll
        for (int mt = 0; mt < 2; mt++) {
            rs[mt][0] += __shfl_xor_sync(0xFFFFFFFF, rs[mt][0], d);
            rs[mt][1] += __shfl_xor_sync(0xFFFFFFFF, rs[mt][1], d);
        }
    }
    __syncthreads();
    if (tig == 0) {
#pragma unroll
        for (int mt = 0; mt < 2; mt++) {
            sred[(wm * 32 + mt * 16 + g) * 2 + wn]     = rs[mt][0];
            sred[(wm * 32 + mt * 16 + g + 8) * 2 + wn] = rs[mt][1];
        }
    }
    __syncthreads();
    if (tid < 128)
        g_spart[(size_t)(m0 + tid) * NB + nb] = sred[tid * 2] + sred[tid * 2 + 1];
}

// ---------------------------------------------------------------------------
// Fused softmax + weighted sum. grid (4, 128).
// ---------------------------------------------------------------------------
__global__ __launch_bounds__(256) void wsum_kernel(const float* __restrict__ x,
                                                   float* __restrict__ out)
{
    __shared__ float w[SL];
    __shared__ int   idxs[SL];
    __shared__ float red[256];
    const int b = blockIdx.y;
    const int t = threadIdx.x;
    const int col = blockIdx.x * 256 + t;
    const float* xb = x + (size_t)b * SL * HD;

    const int cnt  = g_cnt[b];
    const int boff = g_boff[b];

    if (cnt == 0) {
        float acc = 0.0f;
        for (int s = 0; s < SL; s++) acc += xb[(size_t)s * HD + col];
        out[(size_t)b * HD + col] = acc * (1.0f / SL);
        return;
    }

    for (int i = t; i < cnt; i += 256) {
        const int d = boff + i;
        float sc = 0.0f;
#pragma unroll
        for (int p = 0; p < NB; p++) sc += g_spart[(size_t)d * NB + p];
        w[i] = sc;
        idxs[i] = g_src[d] - b * SL;
    }
    __syncthreads();

    float mx = -3.4e38f;
    for (int i = t; i < cnt; i += 256) mx = fmaxf(mx, w[i]);
    red[t] = mx;
    __syncthreads();
    for (int off = 128; off > 0; off >>= 1) {
        if (t < off) red[t] = fmaxf(red[t], red[t + off]);
        __syncthreads();
    }
    const float gm = red[0];
    __syncthreads();

    float ps = 0.0f;
    for (int i = t; i < cnt; i += 256) {
        const float e = __expf(w[i] - gm);
        w[i] = e;
        ps += e;
    }
    red[t] = ps;
    __syncthreads();
    for (int off = 128; off > 0; off >>= 1) {
        if (t < off) red[t] += red[t + off];
        __syncthreads();
    }
    const float inv = 1.0f / red[0];

    float acc = 0.0f;
    int i = 0;
    for (; i + 4 <= cnt; i += 4) {
        const float x0 = __ldg(xb + (size_t)idxs[i]     * HD + col);
        const float x1 = __ldg(xb + (size_t)idxs[i + 1] * HD + col);
        const float x2 = __ldg(xb + (size_t)idxs[i + 2] * HD + col);
        const float x3 = __ldg(xb + (size_t)idxs[i + 3] * HD + col);
        acc += w[i] * x0 + w[i + 1] * x1 + w[i + 2] * x2 + w[i + 3] * x3;
    }
    for (; i < cnt; i++)
        acc += w[i] * __ldg(xb + (size_t)idxs[i] * HD + col);

    out[(size_t)b * HD + col] = acc * inv;
}

// ---------------------------------------------------------------------------
extern "C" void kernel_launch(void* const* d_in, const int* in_sizes, int n_in,
                              void* d_out, int out_size)
{
    const float* x    = (const float*)d_in[0];   // [128,512,1024] f32
    const int*   mask = (const int*)  d_in[1];   // [128,512] int32
    const float* Wq   = (const float*)d_in[2];   // [512,1024] f32
    const float* bq   = (const float*)d_in[3];   // [512] f32
    const float* vq   = (const float*)d_in[4];   // [512] f32
    float* out = (float*)d_out;                  // [128,1024] f32

    cudaFuncSetAttribute(gemm_kernel, cudaFuncAttributeMaxDynamicSharedMemorySize, SMEM_GEMM);

    map_kernel<<<BS, SL>>>(mask);
    conv_kernel<<<16384, 256>>>(x, Wq);
    gemm_kernel<<<dim3(NB, MAX_TILES), 256, SMEM_GEMM>>>(bq, vq);
    wsum_kernel<<<dim3(4, BS), 256>>>(x, out);
}

// round 14
// speedup vs baseline: 1.0394x; 1.0394x over previous
#include <cuda_runtime.h>
#include <cuda_fp16.h>
#include <math.h>
#include <stdint.h>

#define BS 128
#define SL 512
#define HD 1024
#define DD 512
#define M_TOTAL (BS * SL)          // 65536
#define KPHYS 2048                 // [hi | lo] physical K (halves)
#define NEG_FILL -1000000.0f

#define BM 128
#define BN 128
#define NB (DD / BN)               // 4 n-blocks
#define BK 32                      // fp32 cols per chunk (32 hi + 32 lo halves)
#define NCHUNK_P 32                // 1024 / 32
#define STAGES 3
#define T_BYTES (128 * BK * 2)     // 8192
#define A_HI 0
#define A_LO T_BYTES
#define B_HI (2 * T_BYTES)
#define B_LO (3 * T_BYTES)
#define STAGE_BYTES (4 * T_BYTES)  // 32768
#define SMEM_RED (128 * 2 * 4)
#define SMEM_GEMM (STAGES * STAGE_BYTES + SMEM_RED)   // 99328 -> 2 CTAs/SM
#define MAX_TILES (M_TOTAL / BM)   // 512

// 64-byte row swizzle: 4 x 16B blocks per row, phase by (row>>1)&3
#define SW64(r, j) ((r) * 64 + ((((j) ^ (((r) >> 1) & 3))) << 4))

// ---------------- device scratch (no allocations allowed) -------------------
__device__ __half g_A[(size_t)M_TOTAL * KPHYS];   // 268 MB (upper bound)
__device__ __half g_B[(size_t)DD * KPHYS];        // 2 MB
__device__ float  g_spart[M_TOTAL * NB];
__device__ int    g_cnt[BS];
__device__ int    g_boff[BS];
__device__ int    g_total;
__device__ int    g_dst[M_TOTAL];
__device__ int    g_src[M_TOTAL];

// ---------------- helpers ----------------------------------------------------
__device__ __forceinline__ uint32_t smem_u32(const void* p) {
    uint32_t a;
    asm("{ .reg .u64 t; cvta.to.shared.u64 t, %1; cvt.u32.u64 %0, t; }" : "=r"(a) : "l"(p));
    return a;
}
#define CP16(dst, src) \
    asm volatile("cp.async.cg.shared.global [%0], [%1], 16;" :: "r"(dst), "l"(src) : "memory")
#define CP_COMMIT() asm volatile("cp.async.commit_group;" ::: "memory")
#define CP_WAIT1()  asm volatile("cp.async.wait_group 1;" ::: "memory")
#define CP_WAIT0()  asm volatile("cp.async.wait_group 0;" ::: "memory")

__device__ __forceinline__ void ldsm_x4(uint32_t addr, uint32_t& r0, uint32_t& r1,
                                        uint32_t& r2, uint32_t& r3) {
    asm volatile("ldmatrix.sync.aligned.m8n8.x4.shared.b16 {%0,%1,%2,%3}, [%4];"
                 : "=r"(r0), "=r"(r1), "=r"(r2), "=r"(r3) : "r"(addr));
}
__device__ __forceinline__ void mma16816(float* c, const uint32_t* a,
                                         uint32_t b0, uint32_t b1) {
    asm volatile(
        "mma.sync.aligned.m16n8k16.row.col.f32.f16.f16.f32 "
        "{%0,%1,%2,%3},{%4,%5,%6,%7},{%8,%9},{%0,%1,%2,%3};"
        : "+f"(c[0]), "+f"(c[1]), "+f"(c[2]), "+f"(c[3])
        : "r"(a[0]), "r"(a[1]), "r"(a[2]), "r"(a[3]), "r"(b0), "r"(b1));
}

// ---------------------------------------------------------------------------
// Compaction: count, then map (map derives its own cross-batch offset).
// ---------------------------------------------------------------------------
__global__ __launch_bounds__(512) void count_kernel(const int* __restrict__ mask)
{
    const int b = blockIdx.x;
    const int keep = (mask[b * SL + threadIdx.x] == 0);
    const int cnt = __syncthreads_count(keep);
    if (threadIdx.x == 0) g_cnt[b] = cnt;
}

__global__ __launch_bounds__(512) void map_kernel(const int* __restrict__ mask)
{
    __shared__ int pre[SL];
    __shared__ int offs;
    const int b = blockIdx.x, s = threadIdx.x;

    pre[s] = (s < b) ? g_cnt[s] : 0;
    __syncthreads();
    for (int off = 256; off > 0; off >>= 1) {
        if (s < off) pre[s] += pre[s + off];
        __syncthreads();
    }
    if (s == 0) { offs = pre[0]; g_boff[b] = pre[0]; }
    __syncthreads();
    const int my_off = offs;
    __syncthreads();

    const int m = b * SL + s;
    const int v = (mask[m] == 0);
    pre[s] = v;
    __syncthreads();
#pragma unroll
    for (int d = 1; d < SL; d <<= 1) {
        int t = (s >= d) ? pre[s - d] : 0;
        __syncthreads();
        pre[s] += t;
        __syncthreads();
    }
    const int r = my_off + pre[s] - v;
    g_dst[m] = v ? r : -1;
    if (v) g_src[r] = m;
    if (b == BS - 1 && s == SL - 1) g_total = my_off + pre[s];
}

// ---------------------------------------------------------------------------
// Gather + fp32 -> [hi | lo] fp16 split; first 512 blocks also convert Wq.
// ---------------------------------------------------------------------------
__global__ __launch_bounds__(256) void conv_kernel(const float* __restrict__ x,
                                                   const float* __restrict__ Wq)
{
    const int t = threadIdx.x;

    if (blockIdx.x < 512) {
        size_t g = (size_t)blockIdx.x * 256 + t;
        size_t n = g >> 8;
        int kq = (int)(g & 255) << 2;
        float4 v = *reinterpret_cast<const float4*>(Wq + n * HD + kq);

        __half h0 = __float2half_rn(v.x), h1 = __float2half_rn(v.y);
        __half h2 = __float2half_rn(v.z), h3 = __float2half_rn(v.w);
        __half l0 = __float2half_rn(v.x - __half2float(h0));
        __half l1 = __float2half_rn(v.y - __half2float(h1));
        __half l2 = __float2half_rn(v.z - __half2float(h2));
        __half l3 = __float2half_rn(v.w - __half2float(h3));

        __half2* ph = reinterpret_cast<__half2*>(g_B + n * KPHYS + kq);
        __half2* pl = reinterpret_cast<__half2*>(g_B + n * KPHYS + 1024 + kq);
        ph[0] = __halves2half2(h0, h1); ph[1] = __halves2half2(h2, h3);
        pl[0] = __halves2half2(l0, l1); pl[1] = __halves2half2(l2, l3);
    }

    const int total = g_total;
    for (int r = blockIdx.x; r < total; r += 16384) {
        const float* src = x + (size_t)g_src[r] * HD + (t << 2);
        const float4 v = *reinterpret_cast<const float4*>(src);

        __half h0 = __float2half_rn(v.x), h1 = __float2half_rn(v.y);
        __half h2 = __float2half_rn(v.z), h3 = __float2half_rn(v.w);
        __half l0 = __float2half_rn(v.x - __half2float(h0));
        __half l1 = __float2half_rn(v.y - __half2float(h1));
        __half l2 = __float2half_rn(v.z - __half2float(h2));
        __half l3 = __float2half_rn(v.w - __half2float(h3));

        __half2* ph = reinterpret_cast<__half2*>(g_A + (size_t)r * KPHYS + (t << 2));
        __half2* pl = reinterpret_cast<__half2*>(g_A + (size_t)r * KPHYS + 1024 + (t << 2));
        ph[0] = __halves2half2(h0, h1); ph[1] = __halves2half2(h2, h3);
        pl[0] = __halves2half2(l0, l1); pl[1] = __halves2half2(l2, l3);
    }
}

// ---------------------------------------------------------------------------
// GEMM: CTA tile 128x128, 256 threads = 8 warps (4m x 2n), warp tile 32x64,
// BK=32, 2 CTAs/SM, ONE barrier per chunk.
// ---------------------------------------------------------------------------
__device__ __forceinline__ void load_chunk(int chunk, uint32_t stage, int m0, int n0,
                                           int tid)
{
    const int k = chunk * BK;
    const __half* ah = g_A + (size_t)m0 * KPHYS + k;
    const __half* bh = g_B + (size_t)n0 * KPHYS + k;

#pragma unroll
    for (int u = 0; u < 2; u++) {
        int idx = tid + u * 256;
        int r = idx >> 2, j = idx & 3;
        uint32_t sw = SW64(r, j);
        const size_t go = (size_t)r * KPHYS + j * 8;
        CP16(stage + A_HI + sw, ah + go);
        CP16(stage + A_LO + sw, ah + 1024 + go);
        CP16(stage + B_HI + sw, bh + go);
        CP16(stage + B_LO + sw, bh + 1024 + go);
    }
    CP_COMMIT();
}

__global__ __launch_bounds__(256, 2) void gemm_kernel(const float* __restrict__ bq,
                                                      const float* __restrict__ vq)
{
    const int ntiles = (g_total + BM - 1) >> 7;
    if ((int)blockIdx.y >= ntiles) return;

    extern __shared__ char smem[];
    const uint32_t sb = smem_u32(smem);
    const int tid = threadIdx.x;
    const int wid = tid >> 5, lane = tid & 31;
    const int wm = wid & 3, wn = wid >> 2;
    const int m0 = blockIdx.y * BM;
    const int nb = blockIdx.x;
    const int n0 = nb * BN;

    float acc[2][8][4];
#pragma unroll
    for (int i = 0; i < 2; i++)
#pragma unroll
        for (int j = 0; j < 8; j++)
#pragma unroll
            for (int k = 0; k < 4; k++) acc[i][j][k] = 0.0f;

    const int arow = wm * 32 + (lane & 15);
    const int aj   = (lane >> 4);
    const int brow = wn * 64 + (lane & 7) + ((lane >> 4) & 1) * 8;
    const int bj   = ((lane >> 3) & 1);

    load_chunk(0, sb + 0 * STAGE_BYTES, m0, n0, tid);
    load_chunk(1, sb + 1 * STAGE_BYTES, m0, n0, tid);

#pragma unroll 1
    for (int i = 0; i < NCHUNK_P; i++) {
        if (i == NCHUNK_P - 1) { CP_WAIT0(); } else { CP_WAIT1(); }
        __syncthreads();     // chunk i resident; all warps done with chunk i-1

        if (i + 2 < NCHUNK_P)
            load_chunk(i + 2, sb + ((i + 2) % 3) * STAGE_BYTES, m0, n0, tid);

        const uint32_t st = sb + (i % 3) * STAGE_BYTES;

#pragma unroll
        for (int kk = 0; kk < 2; kk++) {
            uint32_t ah0[4], ah1[4], al0[4], al1[4];
            const int j = kk * 2 + aj;
            {
                int r = arow;
                uint32_t sw = SW64(r, j);
                ldsm_x4(st + A_HI + sw, ah0[0], ah0[1], ah0[2], ah0[3]);
                ldsm_x4(st + A_LO + sw, al0[0], al0[1], al0[2], al0[3]);
                r = arow + 16;
                sw = SW64(r, j);
                ldsm_x4(st + A_HI + sw, ah1[0], ah1[1], ah1[2], ah1[3]);
                ldsm_x4(st + A_LO + sw, al1[0], al1[1], al1[2], al1[3]);
            }
#pragma unroll
            for (int nt2 = 0; nt2 < 4; nt2++) {
                const int r = brow + nt2 * 16;
                const int jb = kk * 2 + bj;
                const uint32_t sw = SW64(r, jb);
                uint32_t h0, h1, h2, h3, l0, l1, l2, l3;
                ldsm_x4(st + B_HI + sw, h0, h1, h2, h3);
                ldsm_x4(st + B_LO + sw, l0, l1, l2, l3);
                mma16816(acc[0][2 * nt2],     ah0, h0, h1);
                mma16816(acc[0][2 * nt2 + 1], ah0, h2, h3);
                mma16816(acc[1][2 * nt2],     ah1, h0, h1);
                mma16816(acc[1][2 * nt2 + 1], ah1, h2, h3);
                mma16816(acc[0][2 * nt2],     al0, h0, h1);
                mma16816(acc[0][2 * nt2 + 1], al0, h2, h3);
                mma16816(acc[1][2 * nt2],     al1, h0, h1);
                mma16816(acc[1][2 * nt2 + 1], al1, h2, h3);
                mma16816(acc[0][2 * nt2],     ah0, l0, l1);
                mma16816(acc[0][2 * nt2 + 1], ah0, l2, l3);
                mma16816(acc[1][2 * nt2],     ah1, l0, l1);
                mma16816(acc[1][2 * nt2 + 1], ah1, l2, l3);
            }
        }
    }

    // ---- epilogue: per-row sum of vq[n]*tanh(D+bq[n]) over this 128-n block ----
    float* sred = reinterpret_cast<float*>(smem + STAGES * STAGE_BYTES);
    const int g = lane >> 2, tig = lane & 3;

    float rs[2][2] = {{0.f, 0.f}, {0.f, 0.f}};
#pragma unroll
    for (int mt = 0; mt < 2; mt++) {
#pragma unroll
        for (int nt = 0; nt < 8; nt++) {
            const int n = n0 + wn * 64 + nt * 8 + 2 * tig;
            const float b0 = __ldg(bq + n), b1 = __ldg(bq + n + 1);
            const float v0 = __ldg(vq + n), v1 = __ldg(vq + n + 1);
            rs[mt][0] += v0 * tanhf(acc[mt][nt][0] + b0) + v1 * tanhf(acc[mt][nt][1] + b1);
            rs[mt][1] += v0 * tanhf(acc[mt][nt][2] + b0) + v1 * tanhf(acc[mt][nt][3] + b1);
        }
    }
#pragma unroll
    for (int d = 1; d <= 2; d <<= 1) {
#pragma unroll
        for (int mt = 0; mt < 2; mt++) {
            rs[mt][0] += __shfl_xor_sync(0xFFFFFFFF, rs[mt][0], d);
            rs[mt][1] += __shfl_xor_sync(0xFFFFFFFF, rs[mt][1], d);
        }
    }
    __syncthreads();        // all ldsm/MMA done before sred reuse
    if (tig == 0) {
#pragma unroll
        for (int mt = 0; mt < 2; mt++) {
            sred[(wm * 32 + mt * 16 + g) * 2 + wn]     = rs[mt][0];
            sred[(wm * 32 + mt * 16 + g + 8) * 2 + wn] = rs[mt][1];
        }
    }
    __syncthreads();
    if (tid < 128)
        g_spart[(size_t)(m0 + tid) * NB + nb] = sred[tid * 2] + sred[tid * 2 + 1];
}

// ---------------------------------------------------------------------------
// Fused softmax + weighted sum. grid (4, 128). 8-deep unrolled gathers.
// ---------------------------------------------------------------------------
__global__ __launch_bounds__(256) void wsum_kernel(const float* __restrict__ x,
                                                   float* __restrict__ out)
{
    __shared__ float w[SL];
    __shared__ int   idxs[SL];
    __shared__ float red[256];
    const int b = blockIdx.y;
    const int t = threadIdx.x;
    const int col = blockIdx.x * 256 + t;
    const float* xb = x + (size_t)b * SL * HD;

    const int cnt  = g_cnt[b];
    const int boff = g_boff[b];

    if (cnt == 0) {
        float acc = 0.0f;
        for (int s = 0; s < SL; s++) acc += xb[(size_t)s * HD + col];
        out[(size_t)b * HD + col] = acc * (1.0f / SL);
        return;
    }

    for (int i = t; i < cnt; i += 256) {
        const int d = boff + i;
        float sc = 0.0f;
#pragma unroll
        for (int p = 0; p < NB; p++) sc += g_spart[(size_t)d * NB + p];
        w[i] = sc;
        idxs[i] = g_src[d] - b * SL;
    }
    __syncthreads();

    float mx = -3.4e38f;
    for (int i = t; i < cnt; i += 256) mx = fmaxf(mx, w[i]);
    red[t] = mx;
    __syncthreads();
    for (int off = 128; off > 0; off >>= 1) {
        if (t < off) red[t] = fmaxf(red[t], red[t + off]);
        __syncthreads();
    }
    const float gm = red[0];
    __syncthreads();

    float ps = 0.0f;
    for (int i = t; i < cnt; i += 256) {
        const float e = __expf(w[i] - gm);
        w[i] = e;
        ps += e;
    }
    red[t] = ps;
    __syncthreads();
    for (int off = 128; off > 0; off >>= 1) {
        if (t < off) red[t] += red[t + off];
        __syncthreads();
    }
    const float inv = 1.0f / red[0];

    // weighted sum, 8 outstanding gathered loads per thread
    float acc = 0.0f;
    int i = 0;
    for (; i + 8 <= cnt; i += 8) {
        const float x0 = __ldg(xb + (size_t)idxs[i]     * HD + col);
        const float x1 = __ldg(xb + (size_t)idxs[i + 1] * HD + col);
        const float x2 = __ldg(xb + (size_t)idxs[i + 2] * HD + col);
        const float x3 = __ldg(xb + (size_t)idxs[i + 3] * HD + col);
        const float x4 = __ldg(xb + (size_t)idxs[i + 4] * HD + col);
        const float x5 = __ldg(xb + (size_t)idxs[i + 5] * HD + col);
        const float x6 = __ldg(xb + (size_t)idxs[i + 6] * HD + col);
        const float x7 = __ldg(xb + (size_t)idxs[i + 7] * HD + col);
        acc += w[i]     * x0 + w[i + 1] * x1 + w[i + 2] * x2 + w[i + 3] * x3;
        acc += w[i + 4] * x4 + w[i + 5] * x5 + w[i + 6] * x6 + w[i + 7] * x7;
    }
    for (; i < cnt; i++)
        acc += w[i] * __ldg(xb + (size_t)idxs[i] * HD + col);

    out[(size_t)b * HD + col] = acc * inv;
}

// ---------------------------------------------------------------------------
extern "C" void kernel_launch(void* const* d_in, const int* in_sizes, int n_in,
                              void* d_out, int out_size)
{
    const float* x    = (const float*)d_in[0];   // [128,512,1024] f32
    const int*   mask = (const int*)  d_in[1];   // [128,512] int32
    const float* Wq   = (const float*)d_in[2];   // [512,1024] f32
    const float* bq   = (const float*)d_in[3];   // [512] f32
    const float* vq   = (const float*)d_in[4];   // [512] f32
    float* out = (float*)d_out;                  // [128,1024] f32

    cudaFuncSetAttribute(gemm_kernel, cudaFuncAttributeMaxDynamicSharedMemorySize, SMEM_GEMM);

    count_kernel<<<BS, SL>>>(mask);
    map_kernel<<<BS, SL>>>(mask);
    conv_kernel<<<16384, 256>>>(x, Wq);
    gemm_kernel<<<dim3(NB, MAX_TILES), 256, SMEM_GEMM>>>(bq, vq);
    wsum_kernel<<<dim3(4, BS), 256>>>(x, out);
}

// round 15
// speedup vs baseline: 1.0589x; 1.0188x over previous
#include <cuda_runtime.h>
#include <cuda_fp16.h>
#include <math.h>
#include <stdint.h>

#define BS 128
#define SL 512
#define HD 1024
#define DD 512
#define M_TOTAL (BS * SL)          // 65536
#define KPHYS 2048                 // [hi | lo] physical K (halves)
#define NEG_FILL -1000000.0f

#define BM 128
#define BN 128
#define NB (DD / BN)               // 4 n-blocks
#define BK 32                      // fp32 cols per chunk (32 hi + 32 lo halves)
#define NCHUNK_P 32                // 1024 / 32
#define STAGES 3
#define T_BYTES (128 * BK * 2)     // 8192
#define A_HI 0
#define A_LO T_BYTES
#define B_HI (2 * T_BYTES)
#define B_LO (3 * T_BYTES)
#define STAGE_BYTES (4 * T_BYTES)  // 32768
#define SMEM_RED (128 * 2 * 4)
#define SMEM_GEMM (STAGES * STAGE_BYTES + SMEM_RED)   // 99328 -> 2 CTAs/SM
#define MAX_TILES (M_TOTAL / BM)   // 512

// 64-byte row swizzle: 4 x 16B blocks per row, phase by (row>>1)&3
#define SW64(r, j) ((r) * 64 + ((((j) ^ (((r) >> 1) & 3))) << 4))

// ---------------- device scratch (no allocations allowed) -------------------
__device__ __half g_A[(size_t)M_TOTAL * KPHYS];   // 268 MB (upper bound)
__device__ __half g_B[(size_t)DD * KPHYS];        // 2 MB
__device__ float  g_spart[M_TOTAL * NB];
__device__ int    g_cnt[BS];
__device__ int    g_boff[BS];
__device__ int    g_total;
__device__ int    g_dst[M_TOTAL];
__device__ int    g_src[M_TOTAL];

// ---------------- helpers ----------------------------------------------------
__device__ __forceinline__ uint32_t smem_u32(const void* p) {
    uint32_t a;
    asm("{ .reg .u64 t; cvta.to.shared.u64 t, %1; cvt.u32.u64 %0, t; }" : "=r"(a) : "l"(p));
    return a;
}
#define CP16(dst, src) \
    asm volatile("cp.async.cg.shared.global [%0], [%1], 16;" :: "r"(dst), "l"(src) : "memory")
#define CP_COMMIT() asm volatile("cp.async.commit_group;" ::: "memory")
#define CP_WAIT1()  asm volatile("cp.async.wait_group 1;" ::: "memory")
#define CP_WAIT0()  asm volatile("cp.async.wait_group 0;" ::: "memory")

__device__ __forceinline__ void ldsm_x4(uint32_t addr, uint32_t& r0, uint32_t& r1,
                                        uint32_t& r2, uint32_t& r3) {
    asm volatile("ldmatrix.sync.aligned.m8n8.x4.shared.b16 {%0,%1,%2,%3}, [%4];"
                 : "=r"(r0), "=r"(r1), "=r"(r2), "=r"(r3) : "r"(addr));
}
__device__ __forceinline__ void mma16816(float* c, const uint32_t* a,
                                         uint32_t b0, uint32_t b1) {
    asm volatile(
        "mma.sync.aligned.m16n8k16.row.col.f32.f16.f16.f32 "
        "{%0,%1,%2,%3},{%4,%5,%6,%7},{%8,%9},{%0,%1,%2,%3};"
        : "+f"(c[0]), "+f"(c[1]), "+f"(c[2]), "+f"(c[3])
        : "r"(a[0]), "r"(a[1]), "r"(a[2]), "r"(a[3]), "r"(b0), "r"(b1));
}

// ---------------------------------------------------------------------------
// Compaction: count, then map (map derives its own cross-batch offset).
// ---------------------------------------------------------------------------
__global__ __launch_bounds__(512) void count_kernel(const int* __restrict__ mask)
{
    const int b = blockIdx.x;
    const int keep = (mask[b * SL + threadIdx.x] == 0);
    const int cnt = __syncthreads_count(keep);
    if (threadIdx.x == 0) g_cnt[b] = cnt;
}

__global__ __launch_bounds__(512) void map_kernel(const int* __restrict__ mask)
{
    __shared__ int pre[SL];
    __shared__ int offs;
    const int b = blockIdx.x, s = threadIdx.x;

    pre[s] = (s < b) ? g_cnt[s] : 0;
    __syncthreads();
    for (int off = 256; off > 0; off >>= 1) {
        if (s < off) pre[s] += pre[s + off];
        __syncthreads();
    }
    if (s == 0) { offs = pre[0]; g_boff[b] = pre[0]; }
    __syncthreads();
    const int my_off = offs;
    __syncthreads();

    const int m = b * SL + s;
    const int v = (mask[m] == 0);
    pre[s] = v;
    __syncthreads();
#pragma unroll
    for (int d = 1; d < SL; d <<= 1) {
        int t = (s >= d) ? pre[s - d] : 0;
        __syncthreads();
        pre[s] += t;
        __syncthreads();
    }
    const int r = my_off + pre[s] - v;
    g_dst[m] = v ? r : -1;
    if (v) g_src[r] = m;
    if (b == BS - 1 && s == SL - 1) g_total = my_off + pre[s];
}

// ---------------------------------------------------------------------------
// Gather + fp32 -> [hi | lo] fp16 split; first 512 blocks also convert Wq.
// ---------------------------------------------------------------------------
__global__ __launch_bounds__(256) void conv_kernel(const float* __restrict__ x,
                                                   const float* __restrict__ Wq)
{
    const int t = threadIdx.x;

    if (blockIdx.x < 512) {
        size_t g = (size_t)blockIdx.x * 256 + t;
        size_t n = g >> 8;
        int kq = (int)(g & 255) << 2;
        float4 v = *reinterpret_cast<const float4*>(Wq + n * HD + kq);

        __half h0 = __float2half_rn(v.x), h1 = __float2half_rn(v.y);
        __half h2 = __float2half_rn(v.z), h3 = __float2half_rn(v.w);
        __half l0 = __float2half_rn(v.x - __half2float(h0));
        __half l1 = __float2half_rn(v.y - __half2float(h1));
        __half l2 = __float2half_rn(v.z - __half2float(h2));
        __half l3 = __float2half_rn(v.w - __half2float(h3));

        __half2* ph = reinterpret_cast<__half2*>(g_B + n * KPHYS + kq);
        __half2* pl = reinterpret_cast<__half2*>(g_B + n * KPHYS + 1024 + kq);
        ph[0] = __halves2half2(h0, h1); ph[1] = __halves2half2(h2, h3);
        pl[0] = __halves2half2(l0, l1); pl[1] = __halves2half2(l2, l3);
    }

    const int total = g_total;
    for (int r = blockIdx.x; r < total; r += 16384) {
        const float* src = x + (size_t)g_src[r] * HD + (t << 2);
        const float4 v = *reinterpret_cast<const float4*>(src);

        __half h0 = __float2half_rn(v.x), h1 = __float2half_rn(v.y);
        __half h2 = __float2half_rn(v.z), h3 = __float2half_rn(v.w);
        __half l0 = __float2half_rn(v.x - __half2float(h0));
        __half l1 = __float2half_rn(v.y - __half2float(h1));
        __half l2 = __float2half_rn(v.z - __half2float(h2));
        __half l3 = __float2half_rn(v.w - __half2float(h3));

        __half2* ph = reinterpret_cast<__half2*>(g_A + (size_t)r * KPHYS + (t << 2));
        __half2* pl = reinterpret_cast<__half2*>(g_A + (size_t)r * KPHYS + 1024 + (t << 2));
        ph[0] = __halves2half2(h0, h1); ph[1] = __halves2half2(h2, h3);
        pl[0] = __halves2half2(l0, l1); pl[1] = __halves2half2(l2, l3);
    }
}

// ---------------------------------------------------------------------------
// GEMM: CTA tile 128x128, 256 threads = 8 warps (4m x 2n), warp tile 32x64,
// BK=32, 2 CTAs/SM, ONE barrier per chunk.
// ---------------------------------------------------------------------------
__device__ __forceinline__ void load_chunk(int chunk, uint32_t stage, int m0, int n0,
                                           int tid)
{
    const int k = chunk * BK;
    const __half* ah = g_A + (size_t)m0 * KPHYS + k;
    const __half* bh = g_B + (size_t)n0 * KPHYS + k;

#pragma unroll
    for (int u = 0; u < 2; u++) {
        int idx = tid + u * 256;
        int r = idx >> 2, j = idx & 3;
        uint32_t sw = SW64(r, j);
        const size_t go = (size_t)r * KPHYS + j * 8;
        CP16(stage + A_HI + sw, ah + go);
        CP16(stage + A_LO + sw, ah + 1024 + go);
        CP16(stage + B_HI + sw, bh + go);
        CP16(stage + B_LO + sw, bh + 1024 + go);
    }
    CP_COMMIT();
}

__global__ __launch_bounds__(256, 2) void gemm_kernel(const float* __restrict__ bq,
                                                      const float* __restrict__ vq)
{
    const int ntiles = (g_total + BM - 1) >> 7;
    if ((int)blockIdx.y >= ntiles) return;

    extern __shared__ char smem[];
    const uint32_t sb = smem_u32(smem);
    const int tid = threadIdx.x;
    const int wid = tid >> 5, lane = tid & 31;
    const int wm = wid & 3, wn = wid >> 2;
    const int m0 = blockIdx.y * BM;
    const int nb = blockIdx.x;
    const int n0 = nb * BN;

    float acc[2][8][4];
#pragma unroll
    for (int i = 0; i < 2; i++)
#pragma unroll
        for (int j = 0; j < 8; j++)
#pragma unroll
            for (int k = 0; k < 4; k++) acc[i][j][k] = 0.0f;

    const int arow = wm * 32 + (lane & 15);
    const int aj   = (lane >> 4);
    const int brow = wn * 64 + (lane & 7) + ((lane >> 4) & 1) * 8;
    const int bj   = ((lane >> 3) & 1);

    load_chunk(0, sb + 0 * STAGE_BYTES, m0, n0, tid);
    load_chunk(1, sb + 1 * STAGE_BYTES, m0, n0, tid);

#pragma unroll 1
    for (int i = 0; i < NCHUNK_P; i++) {
        if (i == NCHUNK_P - 1) { CP_WAIT0(); } else { CP_WAIT1(); }
        __syncthreads();     // chunk i resident; all warps done with chunk i-1

        if (i + 2 < NCHUNK_P)
            load_chunk(i + 2, sb + ((i + 2) % 3) * STAGE_BYTES, m0, n0, tid);

        const uint32_t st = sb + (i % 3) * STAGE_BYTES;

#pragma unroll
        for (int kk = 0; kk < 2; kk++) {
            uint32_t ah0[4], ah1[4], al0[4], al1[4];
            const int j = kk * 2 + aj;
            {
                int r = arow;
                uint32_t sw = SW64(r, j);
                ldsm_x4(st + A_HI + sw, ah0[0], ah0[1], ah0[2], ah0[3]);
                ldsm_x4(st + A_LO + sw, al0[0], al0[1], al0[2], al0[3]);
                r = arow + 16;
                sw = SW64(r, j);
                ldsm_x4(st + A_HI + sw, ah1[0], ah1[1], ah1[2], ah1[3]);
                ldsm_x4(st + A_LO + sw, al1[0], al1[1], al1[2], al1[3]);
            }
#pragma unroll
            for (int nt2 = 0; nt2 < 4; nt2++) {
                const int r = brow + nt2 * 16;
                const int jb = kk * 2 + bj;
                const uint32_t sw = SW64(r, jb);
                uint32_t h0, h1, h2, h3, l0, l1, l2, l3;
                ldsm_x4(st + B_HI + sw, h0, h1, h2, h3);
                ldsm_x4(st + B_LO + sw, l0, l1, l2, l3);
                mma16816(acc[0][2 * nt2],     ah0, h0, h1);
                mma16816(acc[0][2 * nt2 + 1], ah0, h2, h3);
                mma16816(acc[1][2 * nt2],     ah1, h0, h1);
                mma16816(acc[1][2 * nt2 + 1], ah1, h2, h3);
                mma16816(acc[0][2 * nt2],     al0, h0, h1);
                mma16816(acc[0][2 * nt2 + 1], al0, h2, h3);
                mma16816(acc[1][2 * nt2],     al1, h0, h1);
                mma16816(acc[1][2 * nt2 + 1], al1, h2, h3);
                mma16816(acc[0][2 * nt2],     ah0, l0, l1);
                mma16816(acc[0][2 * nt2 + 1], ah0, l2, l3);
                mma16816(acc[1][2 * nt2],     ah1, l0, l1);
                mma16816(acc[1][2 * nt2 + 1], ah1, l2, l3);
            }
        }
    }

    // ---- epilogue: per-row sum of vq[n]*tanh(D+bq[n]) over this 128-n block ----
    float* sred = reinterpret_cast<float*>(smem + STAGES * STAGE_BYTES);
    const int g = lane >> 2, tig = lane & 3;

    float rs[2][2] = {{0.f, 0.f}, {0.f, 0.f}};
#pragma unroll
    for (int mt = 0; mt < 2; mt++) {
#pragma unroll
        for (int nt = 0; nt < 8; nt++) {
            const int n = n0 + wn * 64 + nt * 8 + 2 * tig;
            const float b0 = __ldg(bq + n), b1 = __ldg(bq + n + 1);
            const float v0 = __ldg(vq + n), v1 = __ldg(vq + n + 1);
            rs[mt][0] += v0 * tanhf(acc[mt][nt][0] + b0) + v1 * tanhf(acc[mt][nt][1] + b1);
            rs[mt][1] += v0 * tanhf(acc[mt][nt][2] + b0) + v1 * tanhf(acc[mt][nt][3] + b1);
        }
    }
#pragma unroll
    for (int d = 1; d <= 2; d <<= 1) {
#pragma unroll
        for (int mt = 0; mt < 2; mt++) {
            rs[mt][0] += __shfl_xor_sync(0xFFFFFFFF, rs[mt][0], d);
            rs[mt][1] += __shfl_xor_sync(0xFFFFFFFF, rs[mt][1], d);
        }
    }
    __syncthreads();        // all ldsm/MMA done before sred reuse
    if (tig == 0) {
#pragma unroll
        for (int mt = 0; mt < 2; mt++) {
            sred[(wm * 32 + mt * 16 + g) * 2 + wn]     = rs[mt][0];
            sred[(wm * 32 + mt * 16 + g + 8) * 2 + wn] = rs[mt][1];
        }
    }
    __syncthreads();
    if (tid < 128)
        g_spart[(size_t)(m0 + tid) * NB + nb] = sred[tid * 2] + sred[tid * 2 + 1];
}

// ---------------------------------------------------------------------------
// Fused softmax + weighted sum. grid (4, 128). 16-deep unrolled gathers.
// ---------------------------------------------------------------------------
__global__ __launch_bounds__(256) void wsum_kernel(const float* __restrict__ x,
                                                   float* __restrict__ out)
{
    __shared__ float w[SL];
    __shared__ int   idxs[SL];
    __shared__ float red[256];
    const int b = blockIdx.y;
    const int t = threadIdx.x;
    const int col = blockIdx.x * 256 + t;
    const float* xb = x + (size_t)b * SL * HD;

    const int cnt  = g_cnt[b];
    const int boff = g_boff[b];

    if (cnt == 0) {
        float acc = 0.0f;
        for (int s = 0; s < SL; s++) acc += xb[(size_t)s * HD + col];
        out[(size_t)b * HD + col] = acc * (1.0f / SL);
        return;
    }

    for (int i = t; i < cnt; i += 256) {
        const int d = boff + i;
        float sc = 0.0f;
#pragma unroll
        for (int p = 0; p < NB; p++) sc += g_spart[(size_t)d * NB + p];
        w[i] = sc;
        idxs[i] = g_src[d] - b * SL;
    }
    __syncthreads();

    float mx = -3.4e38f;
    for (int i = t; i < cnt; i += 256) mx = fmaxf(mx, w[i]);
    red[t] = mx;
    __syncthreads();
    for (int off = 128; off > 0; off >>= 1) {
        if (t < off) red[t] = fmaxf(red[t], red[t + off]);
        __syncthreads();
    }
    const float gm = red[0];
    __syncthreads();

    float ps = 0.0f;
    for (int i = t; i < cnt; i += 256) {
        const float e = __expf(w[i] - gm);
        w[i] = e;
        ps += e;
    }
    red[t] = ps;
    __syncthreads();
    for (int off = 128; off > 0; off >>= 1) {
        if (t < off) red[t] += red[t + off];
        __syncthreads();
    }
    const float inv = 1.0f / red[0];

    // weighted sum, 16 outstanding gathered loads per thread
    float acc = 0.0f;
    int i = 0;
    for (; i + 16 <= cnt; i += 16) {
        float xv[16];
#pragma unroll
        for (int q = 0; q < 16; q++)
            xv[q] = __ldg(xb + (size_t)idxs[i + q] * HD + col);
#pragma unroll
        for (int q = 0; q < 16; q++)
            acc += w[i + q] * xv[q];
    }
    for (; i + 4 <= cnt; i += 4) {
        const float x0 = __ldg(xb + (size_t)idxs[i]     * HD + col);
        const float x1 = __ldg(xb + (size_t)idxs[i + 1] * HD + col);
        const float x2 = __ldg(xb + (size_t)idxs[i + 2] * HD + col);
        const float x3 = __ldg(xb + (size_t)idxs[i + 3] * HD + col);
        acc += w[i] * x0 + w[i + 1] * x1 + w[i + 2] * x2 + w[i + 3] * x3;
    }
    for (; i < cnt; i++)
        acc += w[i] * __ldg(xb + (size_t)idxs[i] * HD + col);

    out[(size_t)b * HD + col] = acc * inv;
}

// ---------------------------------------------------------------------------
extern "C" void kernel_launch(void* const* d_in, const int* in_sizes, int n_in,
                              void* d_out, int out_size)
{
    const float* x    = (const float*)d_in[0];   // [128,512,1024] f32
    const int*   mask = (const int*)  d_in[1];   // [128,512] int32
    const float* Wq   = (const float*)d_in[2];   // [512,1024] f32
    const float* bq   = (const float*)d_in[3];   // [512] f32
    const float* vq   = (const float*)d_in[4];   // [512] f32
    float* out = (float*)d_out;                  // [128,1024] f32

    cudaFuncSetAttribute(gemm_kernel, cudaFuncAttributeMaxDynamicSharedMemorySize, SMEM_GEMM);

    count_kernel<<<BS, SL>>>(mask);
    map_kernel<<<BS, SL>>>(mask);
    conv_kernel<<<16384, 256>>>(x, Wq);
    gemm_kernel<<<dim3(NB, MAX_TILES), 256, SMEM_GEMM>>>(bq, vq);
    wsum_kernel<<<dim3(4, BS), 256>>>(x, out);
}

// round 16
// speedup vs baseline: 1.0731x; 1.0134x over previous
#include <cuda_runtime.h>
#include <cuda_fp16.h>
#include <math.h>
#include <stdint.h>

#define BS 128
#define SL 512
#define HD 1024
#define DD 512
#define M_TOTAL (BS * SL)          // 65536
#define KPHYS 2048                 // [hi | lo] physical K (halves)
#define NEG_FILL -1000000.0f

#define BM 128
#define BN 128
#define NB (DD / BN)               // 4 n-blocks
#define BK 32                      // fp32 cols per chunk (32 hi + 32 lo halves)
#define NCHUNK_P 32                // 1024 / 32
#define STAGES 3
#define T_BYTES (128 * BK * 2)     // 8192
#define A_HI 0
#define A_LO T_BYTES
#define B_HI (2 * T_BYTES)
#define B_LO (3 * T_BYTES)
#define STAGE_BYTES (4 * T_BYTES)  // 32768
#define SMEM_RED (128 * 2 * 4)
#define SMEM_GEMM (STAGES * STAGE_BYTES + SMEM_RED)   // 99328 -> 2 CTAs/SM
#define MAX_TILES (M_TOTAL / BM)   // 512
#define CONV_GRID 16384

// 64-byte row swizzle: 4 x 16B blocks per row, phase by (row>>1)&3
#define SW64(r, j) ((r) * 64 + ((((j) ^ (((r) >> 1) & 3))) << 4))

// ---------------- device scratch (no allocations allowed) -------------------
__device__ __half g_A[(size_t)M_TOTAL * KPHYS];   // 268 MB (upper bound)
__device__ __half g_B[(size_t)DD * KPHYS];        // 2 MB
__device__ float  g_spart[M_TOTAL * NB];
__device__ int    g_cnt[BS];
__device__ int    g_boff[BS];
__device__ int    g_total;
__device__ int    g_src[M_TOTAL];

// ---------------- helpers ----------------------------------------------------
__device__ __forceinline__ uint32_t smem_u32(const void* p) {
    uint32_t a;
    asm("{ .reg .u64 t; cvta.to.shared.u64 t, %1; cvt.u32.u64 %0, t; }" : "=r"(a) : "l"(p));
    return a;
}
#define CP16(dst, src) \
    asm volatile("cp.async.cg.shared.global [%0], [%1], 16;" :: "r"(dst), "l"(src) : "memory")
#define CP_COMMIT() asm volatile("cp.async.commit_group;" ::: "memory")
#define CP_WAIT1()  asm volatile("cp.async.wait_group 1;" ::: "memory")
#define CP_WAIT0()  asm volatile("cp.async.wait_group 0;" ::: "memory")

__device__ __forceinline__ void ldsm_x4(uint32_t addr, uint32_t& r0, uint32_t& r1,
                                        uint32_t& r2, uint32_t& r3) {
    asm volatile("ldmatrix.sync.aligned.m8n8.x4.shared.b16 {%0,%1,%2,%3}, [%4];"
                 : "=r"(r0), "=r"(r1), "=r"(r2), "=r"(r3) : "r"(addr));
}
__device__ __forceinline__ void mma16816(float* c, const uint32_t* a,
                                         uint32_t b0, uint32_t b1) {
    asm volatile(
        "mma.sync.aligned.m16n8k16.row.col.f32.f16.f16.f32 "
        "{%0,%1,%2,%3},{%4,%5,%6,%7},{%8,%9},{%0,%1,%2,%3};"
        : "+f"(c[0]), "+f"(c[1]), "+f"(c[2]), "+f"(c[3])
        : "r"(a[0]), "r"(a[1]), "r"(a[2]), "r"(a[3]), "r"(b0), "r"(b1));
}
__device__ __forceinline__ void split_store(const float4& v, __half2* ph, __half2* pl)
{
    __half h0 = __float2half_rn(v.x), h1 = __float2half_rn(v.y);
    __half h2 = __float2half_rn(v.z), h3 = __float2half_rn(v.w);
    __half l0 = __float2half_rn(v.x - __half2float(h0));
    __half l1 = __float2half_rn(v.y - __half2float(h1));
    __half l2 = __float2half_rn(v.z - __half2float(h2));
    __half l3 = __float2half_rn(v.w - __half2float(h3));
    ph[0] = __halves2half2(h0, h1); ph[1] = __halves2half2(h2, h3);
    pl[0] = __halves2half2(l0, l1); pl[1] = __halves2half2(l2, l3);
}

// ---------------------------------------------------------------------------
// Compaction: count, then map (map derives its own cross-batch offset).
// ---------------------------------------------------------------------------
__global__ __launch_bounds__(512) void count_kernel(const int* __restrict__ mask)
{
    const int b = blockIdx.x;
    const int keep = (mask[b * SL + threadIdx.x] == 0);
    const int cnt = __syncthreads_count(keep);
    if (threadIdx.x == 0) g_cnt[b] = cnt;
}

__global__ __launch_bounds__(512) void map_kernel(const int* __restrict__ mask)
{
    __shared__ int pre[SL];
    __shared__ int offs;
    const int b = blockIdx.x, s = threadIdx.x;

    pre[s] = (s < b) ? g_cnt[s] : 0;
    __syncthreads();
    for (int off = 256; off > 0; off >>= 1) {
        if (s < off) pre[s] += pre[s + off];
        __syncthreads();
    }
    if (s == 0) { offs = pre[0]; g_boff[b] = pre[0]; }
    __syncthreads();
    const int my_off = offs;
    __syncthreads();

    const int m = b * SL + s;
    const int v = (mask[m] == 0);
    pre[s] = v;
    __syncthreads();
#pragma unroll
    for (int d = 1; d < SL; d <<= 1) {
        int t = (s >= d) ? pre[s - d] : 0;
        __syncthreads();
        pre[s] += t;
        __syncthreads();
    }
    const int r = my_off + pre[s] - v;
    if (v) g_src[r] = m;
    if (b == BS - 1 && s == SL - 1) g_total = my_off + pre[s];
}

// ---------------------------------------------------------------------------
// Gather + fp32 -> [hi | lo] fp16 split, dual-row (MLP=2); first 512 blocks
// also convert Wq.
// ---------------------------------------------------------------------------
__global__ __launch_bounds__(256) void conv_kernel(const float* __restrict__ x,
                                                   const float* __restrict__ Wq)
{
    const int t = threadIdx.x;

    if (blockIdx.x < 512) {
        size_t g = (size_t)blockIdx.x * 256 + t;
        size_t n = g >> 8;
        int kq = (int)(g & 255) << 2;
        float4 v = *reinterpret_cast<const float4*>(Wq + n * HD + kq);
        split_store(v,
            reinterpret_cast<__half2*>(g_B + n * KPHYS + kq),
            reinterpret_cast<__half2*>(g_B + n * KPHYS + 1024 + kq));
    }

    const int total = g_total;
    const int r0 = blockIdx.x;
    const int r1 = blockIdx.x + CONV_GRID;
    const bool v0 = (r0 < total);
    const bool v1 = (r1 < total);

    int s0 = 0, s1 = 0;
    if (v0) s0 = g_src[r0];
    if (v1) s1 = g_src[r1];

    float4 va, vb;
    if (v0) va = *reinterpret_cast<const float4*>(x + (size_t)s0 * HD + (t << 2));
    if (v1) vb = *reinterpret_cast<const float4*>(x + (size_t)s1 * HD + (t << 2));

    if (v0) split_store(va,
        reinterpret_cast<__half2*>(g_A + (size_t)r0 * KPHYS + (t << 2)),
        reinterpret_cast<__half2*>(g_A + (size_t)r0 * KPHYS + 1024 + (t << 2)));
    if (v1) split_store(vb,
        reinterpret_cast<__half2*>(g_A + (size_t)r1 * KPHYS + (t << 2)),
        reinterpret_cast<__half2*>(g_A + (size_t)r1 * KPHYS + 1024 + (t << 2)));
}

// ---------------------------------------------------------------------------
// GEMM: CTA tile 128x128, 256 threads = 8 warps (4m x 2n), warp tile 32x64,
// BK=32, 2 CTAs/SM, ONE barrier per chunk.
// ---------------------------------------------------------------------------
__device__ __forceinline__ void load_chunk(int chunk, uint32_t stage, int m0, int n0,
                                           int tid)
{
    const int k = chunk * BK;
    const __half* ah = g_A + (size_t)m0 * KPHYS + k;
    const __half* bh = g_B + (size_t)n0 * KPHYS + k;

#pragma unroll
    for (int u = 0; u < 2; u++) {
        int idx = tid + u * 256;
        int r = idx >> 2, j = idx & 3;
        uint32_t sw = SW64(r, j);
        const size_t go = (size_t)r * KPHYS + j * 8;
        CP16(stage + A_HI + sw, ah + go);
        CP16(stage + A_LO + sw, ah + 1024 + go);
        CP16(stage + B_HI + sw, bh + go);
        CP16(stage + B_LO + sw, bh + 1024 + go);
    }
    CP_COMMIT();
}

__global__ __launch_bounds__(256, 2) void gemm_kernel(const float* __restrict__ bq,
                                                      const float* __restrict__ vq)
{
    const int ntiles = (g_total + BM - 1) >> 7;
    if ((int)blockIdx.y >= ntiles) return;

    extern __shared__ char smem[];
    const uint32_t sb = smem_u32(smem);
    const int tid = threadIdx.x;
    const int wid = tid >> 5, lane = tid & 31;
    const int wm = wid & 3, wn = wid >> 2;
    const int m0 = blockIdx.y * BM;
    const int nb = blockIdx.x;
    const int n0 = nb * BN;

    float acc[2][8][4];
#pragma unroll
    for (int i = 0; i < 2; i++)
#pragma unroll
        for (int j = 0; j < 8; j++)
#pragma unroll
            for (int k = 0; k < 4; k++) acc[i][j][k] = 0.0f;

    const int arow = wm * 32 + (lane & 15);
    const int aj   = (lane >> 4);
    const int brow = wn * 64 + (lane & 7) + ((lane >> 4) & 1) * 8;
    const int bj   = ((lane >> 3) & 1);

    load_chunk(0, sb + 0 * STAGE_BYTES, m0, n0, tid);
    load_chunk(1, sb + 1 * STAGE_BYTES, m0, n0, tid);

#pragma unroll 1
    for (int i = 0; i < NCHUNK_P; i++) {
        if (i == NCHUNK_P - 1) { CP_WAIT0(); } else { CP_WAIT1(); }
        __syncthreads();     // chunk i resident; all warps done with chunk i-1

        if (i + 2 < NCHUNK_P)
            load_chunk(i + 2, sb + ((i + 2) % 3) * STAGE_BYTES, m0, n0, tid);

        const uint32_t st = sb + (i % 3) * STAGE_BYTES;

#pragma unroll
        for (int kk = 0; kk < 2; kk++) {
            uint32_t ah0[4], ah1[4], al0[4], al1[4];
            const int j = kk * 2 + aj;
            {
                int r = arow;
                uint32_t sw = SW64(r, j);
                ldsm_x4(st + A_HI + sw, ah0[0], ah0[1], ah0[2], ah0[3]);
                ldsm_x4(st + A_LO + sw, al0[0], al0[1], al0[2], al0[3]);
                r = arow + 16;
                sw = SW64(r, j);
                ldsm_x4(st + A_HI + sw, ah1[0], ah1[1], ah1[2], ah1[3]);
                ldsm_x4(st + A_LO + sw, al1[0], al1[1], al1[2], al1[3]);
            }
#pragma unroll
            for (int nt2 = 0; nt2 < 4; nt2++) {
                const int r = brow + nt2 * 16;
                const int jb = kk * 2 + bj;
                const uint32_t sw = SW64(r, jb);
                uint32_t h0, h1, h2, h3, l0, l1, l2, l3;
                ldsm_x4(st + B_HI + sw, h0, h1, h2, h3);
                ldsm_x4(st + B_LO + sw, l0, l1, l2, l3);
                mma16816(acc[0][2 * nt2],     ah0, h0, h1);
                mma16816(acc[0][2 * nt2 + 1], ah0, h2, h3);
                mma16816(acc[1][2 * nt2],     ah1, h0, h1);
                mma16816(acc[1][2 * nt2 + 1], ah1, h2, h3);
                mma16816(acc[0][2 * nt2],     al0, h0, h1);
                mma16816(acc[0][2 * nt2 + 1], al0, h2, h3);
                mma16816(acc[1][2 * nt2],     al1, h0, h1);
                mma16816(acc[1][2 * nt2 + 1], al1, h2, h3);
                mma16816(acc[0][2 * nt2],     ah0, l0, l1);
                mma16816(acc[0][2 * nt2 + 1], ah0, l2, l3);
                mma16816(acc[1][2 * nt2],     ah1, l0, l1);
                mma16816(acc[1][2 * nt2 + 1], ah1, l2, l3);
            }
        }
    }

    // ---- epilogue: per-row sum of vq[n]*tanh(D+bq[n]) over this 128-n block ----
    float* sred = reinterpret_cast<float*>(smem + STAGES * STAGE_BYTES);
    const int g = lane >> 2, tig = lane & 3;

    float rs[2][2] = {{0.f, 0.f}, {0.f, 0.f}};
#pragma unroll
    for (int mt = 0; mt < 2; mt++) {
#pragma unroll
        for (int nt = 0; nt < 8; nt++) {
            const int n = n0 + wn * 64 + nt * 8 + 2 * tig;
            const float b0 = __ldg(bq + n), b1 = __ldg(bq + n + 1);
            const float v0 = __ldg(vq + n), v1 = __ldg(vq + n + 1);
            rs[mt][0] += v0 * tanhf(acc[mt][nt][0] + b0) + v1 * tanhf(acc[mt][nt][1] + b1);
            rs[mt][1] += v0 * tanhf(acc[mt][nt][2] + b0) + v1 * tanhf(acc[mt][nt][3] + b1);
        }
    }
#pragma unroll
    for (int d = 1; d <= 2; d <<= 1) {
#pragma unroll
        for (int mt = 0; mt < 2; mt++) {
            rs[mt][0] += __shfl_xor_sync(0xFFFFFFFF, rs[mt][0], d);
            rs[mt][1] += __shfl_xor_sync(0xFFFFFFFF, rs[mt][1], d);
        }
    }
    __syncthreads();        // all ldsm/MMA done before sred reuse
    if (tig == 0) {
#pragma unroll
        for (int mt = 0; mt < 2; mt++) {
            sred[(wm * 32 + mt * 16 + g) * 2 + wn]     = rs[mt][0];
            sred[(wm * 32 + mt * 16 + g + 8) * 2 + wn] = rs[mt][1];
        }
    }
    __syncthreads();
    if (tid < 128)
        g_spart[(size_t)(m0 + tid) * NB + nb] = sred[tid * 2] + sred[tid * 2 + 1];
}

// ---------------------------------------------------------------------------
// Fused softmax + weighted sum. grid (4, 128). 16-deep unrolled gathers.
// ---------------------------------------------------------------------------
__global__ __launch_bounds__(256) void wsum_kernel(const float* __restrict__ x,
                                                   float* __restrict__ out)
{
    __shared__ float w[SL];
    __shared__ int   idxs[SL];
    __shared__ float red[256];
    const int b = blockIdx.y;
    const int t = threadIdx.x;
    const int col = blockIdx.x * 256 + t;
    const float* xb = x + (size_t)b * SL * HD;

    const int cnt  = g_cnt[b];
    const int boff = g_boff[b];

    if (cnt == 0) {
        float acc = 0.0f;
        for (int s = 0; s < SL; s++) acc += xb[(size_t)s * HD + col];
        out[(size_t)b * HD + col] = acc * (1.0f / SL);
        return;
    }

    for (int i = t; i < cnt; i += 256) {
        const int d = boff + i;
        float sc = 0.0f;
#pragma unroll
        for (int p = 0; p < NB; p++) sc += g_spart[(size_t)d * NB + p];
        w[i] = sc;
        idxs[i] = g_src[d] - b * SL;
    }
    __syncthreads();

    float mx = -3.4e38f;
    for (int i = t; i < cnt; i += 256) mx = fmaxf(mx, w[i]);
    red[t] = mx;
    __syncthreads();
    for (int off = 128; off > 0; off >>= 1) {
        if (t < off) red[t] = fmaxf(red[t], red[t + off]);
        __syncthreads();
    }
    const float gm = red[0];
    __syncthreads();

    float ps = 0.0f;
    for (int i = t; i < cnt; i += 256) {
        const float e = __expf(w[i] - gm);
        w[i] = e;
        ps += e;
    }
    red[t] = ps;
    __syncthreads();
    for (int off = 128; off > 0; off >>= 1) {
        if (t < off) red[t] += red[t + off];
        __syncthreads();
    }
    const float inv = 1.0f / red[0];

    // weighted sum, 16 outstanding gathered loads per thread
    float acc = 0.0f;
    int i = 0;
    for (; i + 16 <= cnt; i += 16) {
        float xv[16];
#pragma unroll
        for (int q = 0; q < 16; q++)
            xv[q] = __ldg(xb + (size_t)idxs[i + q] * HD + col);
#pragma unroll
        for (int q = 0; q < 16; q++)
            acc += w[i + q] * xv[q];
    }
    for (; i + 4 <= cnt; i += 4) {
        const float x0 = __ldg(xb + (size_t)idxs[i]     * HD + col);
        const float x1 = __ldg(xb + (size_t)idxs[i + 1] * HD + col);
        const float x2 = __ldg(xb + (size_t)idxs[i + 2] * HD + col);
        const float x3 = __ldg(xb + (size_t)idxs[i + 3] * HD + col);
        acc += w[i] * x0 + w[i + 1] * x1 + w[i + 2] * x2 + w[i + 3] * x3;
    }
    for (; i < cnt; i++)
        acc += w[i] * __ldg(xb + (size_t)idxs[i] * HD + col);

    out[(size_t)b * HD + col] = acc * inv;
}

// ---------------------------------------------------------------------------
extern "C" void kernel_launch(void* const* d_in, const int* in_sizes, int n_in,
                              void* d_out, int out_size)
{
    const float* x    = (const float*)d_in[0];   // [128,512,1024] f32
    const int*   mask = (const int*)  d_in[1];   // [128,512] int32
    const float* Wq   = (const float*)d_in[2];   // [512,1024] f32
    const float* bq   = (const float*)d_in[3];   // [512] f32
    const float* vq   = (const float*)d_in[4];   // [512] f32
    float* out = (float*)d_out;                  // [128,1024] f32

    cudaFuncSetAttribute(gemm_kernel, cudaFuncAttributeMaxDynamicSharedMemorySize, SMEM_GEMM);

    count_kernel<<<BS, SL>>>(mask);
    map_kernel<<<BS, SL>>>(mask);
    conv_kernel<<<CONV_GRID, 256>>>(x, Wq);
    gemm_kernel<<<dim3(NB, MAX_TILES), 256, SMEM_GEMM>>>(bq, vq);
    wsum_kernel<<<dim3(4, BS), 256>>>(x, out);
}

// round 17
// speedup vs baseline: 1.0738x; 1.0006x over previous
#include <cuda_runtime.h>
#include <cuda_fp16.h>
#include <math.h>
#include <stdint.h>

#define BS 128
#define SL 512
#define HD 1024
#define DD 512
#define M_TOTAL (BS * SL)          // 65536
#define KPHYS 2048                 // [hi | lo] physical K (halves)
#define NEG_FILL -1000000.0f

#define BM 128
#define BN 128
#define NB (DD / BN)               // 4 n-blocks
#define BK 32                      // fp32 cols per chunk (32 hi + 32 lo halves)
#define NCHUNK_P 32                // 1024 / 32
#define STAGES 3
#define T_BYTES (128 * BK * 2)     // 8192
#define A_HI 0
#define A_LO T_BYTES
#define B_HI (2 * T_BYTES)
#define B_LO (3 * T_BYTES)
#define STAGE_BYTES (4 * T_BYTES)  // 32768
#define SMEM_RED (128 * 2 * 4)
#define SMEM_GEMM (STAGES * STAGE_BYTES + SMEM_RED)   // 99328 -> 2 CTAs/SM
#define MAX_TILES (M_TOTAL / BM)   // 512
#define CONV_GRID 8192             // 4 rows per block (MLP=4)

// 64-byte row swizzle: 4 x 16B blocks per row, phase by (row>>1)&3
#define SW64(r, j) ((r) * 64 + ((((j) ^ (((r) >> 1) & 3))) << 4))

// ---------------- device scratch (no allocations allowed) -------------------
__device__ __half g_A[(size_t)M_TOTAL * KPHYS];   // 268 MB (upper bound)
__device__ __half g_B[(size_t)DD * KPHYS];        // 2 MB
__device__ float  g_spart[M_TOTAL * NB];
__device__ int    g_cnt[BS];
__device__ int    g_boff[BS];
__device__ int    g_total;
__device__ int    g_src[M_TOTAL];

// ---------------- helpers ----------------------------------------------------
__device__ __forceinline__ uint32_t smem_u32(const void* p) {
    uint32_t a;
    asm("{ .reg .u64 t; cvta.to.shared.u64 t, %1; cvt.u32.u64 %0, t; }" : "=r"(a) : "l"(p));
    return a;
}
#define CP16(dst, src) \
    asm volatile("cp.async.cg.shared.global [%0], [%1], 16;" :: "r"(dst), "l"(src) : "memory")
#define CP_COMMIT() asm volatile("cp.async.commit_group;" ::: "memory")
#define CP_WAIT1()  asm volatile("cp.async.wait_group 1;" ::: "memory")
#define CP_WAIT0()  asm volatile("cp.async.wait_group 0;" ::: "memory")

__device__ __forceinline__ void ldsm_x4(uint32_t addr, uint32_t& r0, uint32_t& r1,
                                        uint32_t& r2, uint32_t& r3) {
    asm volatile("ldmatrix.sync.aligned.m8n8.x4.shared.b16 {%0,%1,%2,%3}, [%4];"
                 : "=r"(r0), "=r"(r1), "=r"(r2), "=r"(r3) : "r"(addr));
}
__device__ __forceinline__ void mma16816(float* c, const uint32_t* a,
                                         uint32_t b0, uint32_t b1) {
    asm volatile(
        "mma.sync.aligned.m16n8k16.row.col.f32.f16.f16.f32 "
        "{%0,%1,%2,%3},{%4,%5,%6,%7},{%8,%9},{%0,%1,%2,%3};"
        : "+f"(c[0]), "+f"(c[1]), "+f"(c[2]), "+f"(c[3])
        : "r"(a[0]), "r"(a[1]), "r"(a[2]), "r"(a[3]), "r"(b0), "r"(b1));
}
__device__ __forceinline__ void split_store(const float4& v, __half2* ph, __half2* pl)
{
    __half h0 = __float2half_rn(v.x), h1 = __float2half_rn(v.y);
    __half h2 = __float2half_rn(v.z), h3 = __float2half_rn(v.w);
    __half l0 = __float2half_rn(v.x - __half2float(h0));
    __half l1 = __float2half_rn(v.y - __half2float(h1));
    __half l2 = __float2half_rn(v.z - __half2float(h2));
    __half l3 = __float2half_rn(v.w - __half2float(h3));
    ph[0] = __halves2half2(h0, h1); ph[1] = __halves2half2(h2, h3);
    pl[0] = __halves2half2(l0, l1); pl[1] = __halves2half2(l2, l3);
}

// ---------------------------------------------------------------------------
// Compaction: count, then map (map derives its own cross-batch offset).
// ---------------------------------------------------------------------------
__global__ __launch_bounds__(512) void count_kernel(const int* __restrict__ mask)
{
    const int b = blockIdx.x;
    const int keep = (mask[b * SL + threadIdx.x] == 0);
    const int cnt = __syncthreads_count(keep);
    if (threadIdx.x == 0) g_cnt[b] = cnt;
}

__global__ __launch_bounds__(512) void map_kernel(const int* __restrict__ mask)
{
    __shared__ int pre[SL];
    __shared__ int offs;
    const int b = blockIdx.x, s = threadIdx.x;

    pre[s] = (s < b) ? g_cnt[s] : 0;
    __syncthreads();
    for (int off = 256; off > 0; off >>= 1) {
        if (s < off) pre[s] += pre[s + off];
        __syncthreads();
    }
    if (s == 0) { offs = pre[0]; g_boff[b] = pre[0]; }
    __syncthreads();
    const int my_off = offs;
    __syncthreads();

    const int m = b * SL + s;
    const int v = (mask[m] == 0);
    pre[s] = v;
    __syncthreads();
#pragma unroll
    for (int d = 1; d < SL; d <<= 1) {
        int t = (s >= d) ? pre[s - d] : 0;
        __syncthreads();
        pre[s] += t;
        __syncthreads();
    }
    const int r = my_off + pre[s] - v;
    if (v) g_src[r] = m;
    if (b == BS - 1 && s == SL - 1) g_total = my_off + pre[s];
}

// ---------------------------------------------------------------------------
// Gather + fp32 -> [hi | lo] fp16 split, quad-row (MLP=4); first 512 blocks
// also convert Wq.
// ---------------------------------------------------------------------------
__global__ __launch_bounds__(256) void conv_kernel(const float* __restrict__ x,
                                                   const float* __restrict__ Wq)
{
    const int t = threadIdx.x;

    if (blockIdx.x < 512) {
        size_t g = (size_t)blockIdx.x * 256 + t;
        size_t n = g >> 8;
        int kq = (int)(g & 255) << 2;
        float4 v = *reinterpret_cast<const float4*>(Wq + n * HD + kq);
        split_store(v,
            reinterpret_cast<__half2*>(g_B + n * KPHYS + kq),
            reinterpret_cast<__half2*>(g_B + n * KPHYS + 1024 + kq));
    }

    const int total = g_total;
    int   rr[4];
    bool  vv[4];
    int   ss[4];
    float4 vx[4];

#pragma unroll
    for (int q = 0; q < 4; q++) {
        rr[q] = blockIdx.x + q * CONV_GRID;
        vv[q] = (rr[q] < total);
    }
#pragma unroll
    for (int q = 0; q < 4; q++)
        if (vv[q]) ss[q] = g_src[rr[q]];
#pragma unroll
    for (int q = 0; q < 4; q++)
        if (vv[q]) vx[q] = *reinterpret_cast<const float4*>(
                               x + (size_t)ss[q] * HD + (t << 2));
#pragma unroll
    for (int q = 0; q < 4; q++)
        if (vv[q]) split_store(vx[q],
            reinterpret_cast<__half2*>(g_A + (size_t)rr[q] * KPHYS + (t << 2)),
            reinterpret_cast<__half2*>(g_A + (size_t)rr[q] * KPHYS + 1024 + (t << 2)));
}

// ---------------------------------------------------------------------------
// GEMM: CTA tile 128x128, 256 threads = 8 warps (4m x 2n), warp tile 32x64,
// BK=32, 2 CTAs/SM, ONE barrier per chunk.
// ---------------------------------------------------------------------------
__device__ __forceinline__ void load_chunk(int chunk, uint32_t stage, int m0, int n0,
                                           int tid)
{
    const int k = chunk * BK;
    const __half* ah = g_A + (size_t)m0 * KPHYS + k;
    const __half* bh = g_B + (size_t)n0 * KPHYS + k;

#pragma unroll
    for (int u = 0; u < 2; u++) {
        int idx = tid + u * 256;
        int r = idx >> 2, j = idx & 3;
        uint32_t sw = SW64(r, j);
        const size_t go = (size_t)r * KPHYS + j * 8;
        CP16(stage + A_HI + sw, ah + go);
        CP16(stage + A_LO + sw, ah + 1024 + go);
        CP16(stage + B_HI + sw, bh + go);
        CP16(stage + B_LO + sw, bh + 1024 + go);
    }
    CP_COMMIT();
}

__global__ __launch_bounds__(256, 2) void gemm_kernel(const float* __restrict__ bq,
                                                      const float* __restrict__ vq)
{
    const int ntiles = (g_total + BM - 1) >> 7;
    if ((int)blockIdx.y >= ntiles) return;

    extern __shared__ char smem[];
    const uint32_t sb = smem_u32(smem);
    const int tid = threadIdx.x;
    const int wid = tid >> 5, lane = tid & 31;
    const int wm = wid & 3, wn = wid >> 2;
    const int m0 = blockIdx.y * BM;
    const int nb = blockIdx.x;
    const int n0 = nb * BN;

    float acc[2][8][4];
#pragma unroll
    for (int i = 0; i < 2; i++)
#pragma unroll
        for (int j = 0; j < 8; j++)
#pragma unroll
            for (int k = 0; k < 4; k++) acc[i][j][k] = 0.0f;

    const int arow = wm * 32 + (lane & 15);
    const int aj   = (lane >> 4);
    const int brow = wn * 64 + (lane & 7) + ((lane >> 4) & 1) * 8;
    const int bj   = ((lane >> 3) & 1);

    load_chunk(0, sb + 0 * STAGE_BYTES, m0, n0, tid);
    load_chunk(1, sb + 1 * STAGE_BYTES, m0, n0, tid);

#pragma unroll 1
    for (int i = 0; i < NCHUNK_P; i++) {
        if (i == NCHUNK_P - 1) { CP_WAIT0(); } else { CP_WAIT1(); }
        __syncthreads();     // chunk i resident; all warps done with chunk i-1

        if (i + 2 < NCHUNK_P)
            load_chunk(i + 2, sb + ((i + 2) % 3) * STAGE_BYTES, m0, n0, tid);

        const uint32_t st = sb + (i % 3) * STAGE_BYTES;

#pragma unroll
        for (int kk = 0; kk < 2; kk++) {
            uint32_t ah0[4], ah1[4], al0[4], al1[4];
            const int j = kk * 2 + aj;
            {
                int r = arow;
                uint32_t sw = SW64(r, j);
                ldsm_x4(st + A_HI + sw, ah0[0], ah0[1], ah0[2], ah0[3]);
                ldsm_x4(st + A_LO + sw, al0[0], al0[1], al0[2], al0[3]);
                r = arow + 16;
                sw = SW64(r, j);
                ldsm_x4(st + A_HI + sw, ah1[0], ah1[1], ah1[2], ah1[3]);
                ldsm_x4(st + A_LO + sw, al1[0], al1[1], al1[2], al1[3]);
            }
#pragma unroll
            for (int nt2 = 0; nt2 < 4; nt2++) {
                const int r = brow + nt2 * 16;
                const int jb = kk * 2 + bj;
                const uint32_t sw = SW64(r, jb);
                uint32_t h0, h1, h2, h3, l0, l1, l2, l3;
                ldsm_x4(st + B_HI + sw, h0, h1, h2, h3);
                ldsm_x4(st + B_LO + sw, l0, l1, l2, l3);
                mma16816(acc[0][2 * nt2],     ah0, h0, h1);
                mma16816(acc[0][2 * nt2 + 1], ah0, h2, h3);
                mma16816(acc[1][2 * nt2],     ah1, h0, h1);
                mma16816(acc[1][2 * nt2 + 1], ah1, h2, h3);
                mma16816(acc[0][2 * nt2],     al0, h0, h1);
                mma16816(acc[0][2 * nt2 + 1], al0, h2, h3);
                mma16816(acc[1][2 * nt2],     al1, h0, h1);
                mma16816(acc[1][2 * nt2 + 1], al1, h2, h3);
                mma16816(acc[0][2 * nt2],     ah0, l0, l1);
                mma16816(acc[0][2 * nt2 + 1], ah0, l2, l3);
                mma16816(acc[1][2 * nt2],     ah1, l0, l1);
                mma16816(acc[1][2 * nt2 + 1], ah1, l2, l3);
            }
        }
    }

    // ---- epilogue: per-row sum of vq[n]*tanh(D+bq[n]) over this 128-n block ----
    float* sred = reinterpret_cast<float*>(smem + STAGES * STAGE_BYTES);
    const int g = lane >> 2, tig = lane & 3;

    float rs[2][2] = {{0.f, 0.f}, {0.f, 0.f}};
#pragma unroll
    for (int mt = 0; mt < 2; mt++) {
#pragma unroll
        for (int nt = 0; nt < 8; nt++) {
            const int n = n0 + wn * 64 + nt * 8 + 2 * tig;
            const float b0 = __ldg(bq + n), b1 = __ldg(bq + n + 1);
            const float v0 = __ldg(vq + n), v1 = __ldg(vq + n + 1);
            rs[mt][0] += v0 * tanhf(acc[mt][nt][0] + b0) + v1 * tanhf(acc[mt][nt][1] + b1);
            rs[mt][1] += v0 * tanhf(acc[mt][nt][2] + b0) + v1 * tanhf(acc[mt][nt][3] + b1);
        }
    }
#pragma unroll
    for (int d = 1; d <= 2; d <<= 1) {
#pragma unroll
        for (int mt = 0; mt < 2; mt++) {
            rs[mt][0] += __shfl_xor_sync(0xFFFFFFFF, rs[mt][0], d);
            rs[mt][1] += __shfl_xor_sync(0xFFFFFFFF, rs[mt][1], d);
        }
    }
    __syncthreads();        // all ldsm/MMA done before sred reuse
    if (tig == 0) {
#pragma unroll
        for (int mt = 0; mt < 2; mt++) {
            sred[(wm * 32 + mt * 16 + g) * 2 + wn]     = rs[mt][0];
            sred[(wm * 32 + mt * 16 + g + 8) * 2 + wn] = rs[mt][1];
        }
    }
    __syncthreads();
    if (tid < 128)
        g_spart[(size_t)(m0 + tid) * NB + nb] = sred[tid * 2] + sred[tid * 2 + 1];
}

// ---------------------------------------------------------------------------
// Fused softmax + weighted sum. grid (4, 128). 16-deep unrolled gathers.
// ---------------------------------------------------------------------------
__global__ __launch_bounds__(256) void wsum_kernel(const float* __restrict__ x,
                                                   float* __restrict__ out)
{
    __shared__ float w[SL];
    __shared__ int   idxs[SL];
    __shared__ float red[256];
    const int b = blockIdx.y;
    const int t = threadIdx.x;
    const int col = blockIdx.x * 256 + t;
    const float* xb = x + (size_t)b * SL * HD;

    const int cnt  = g_cnt[b];
    const int boff = g_boff[b];

    if (cnt == 0) {
        float acc = 0.0f;
        for (int s = 0; s < SL; s++) acc += xb[(size_t)s * HD + col];
        out[(size_t)b * HD + col] = acc * (1.0f / SL);
        return;
    }

    for (int i = t; i < cnt; i += 256) {
        const int d = boff + i;
        float sc = 0.0f;
#pragma unroll
        for (int p = 0; p < NB; p++) sc += g_spart[(size_t)d * NB + p];
        w[i] = sc;
        idxs[i] = g_src[d] - b * SL;
    }
    __syncthreads();

    float mx = -3.4e38f;
    for (int i = t; i < cnt; i += 256) mx = fmaxf(mx, w[i]);
    red[t] = mx;
    __syncthreads();
    for (int off = 128; off > 0; off >>= 1) {
        if (t < off) red[t] = fmaxf(red[t], red[t + off]);
        __syncthreads();
    }
    const float gm = red[0];
    __syncthreads();

    float ps = 0.0f;
    for (int i = t; i < cnt; i += 256) {
        const float e = __expf(w[i] - gm);
        w[i] = e;
        ps += e;
    }
    red[t] = ps;
    __syncthreads();
    for (int off = 128; off > 0; off >>= 1) {
        if (t < off) red[t] += red[t + off];
        __syncthreads();
    }
    const float inv = 1.0f / red[0];

    // weighted sum, 16 outstanding gathered loads per thread
    float acc = 0.0f;
    int i = 0;
    for (; i + 16 <= cnt; i += 16) {
        float xv[16];
#pragma unroll
        for (int q = 0; q < 16; q++)
            xv[q] = __ldg(xb + (size_t)idxs[i + q] * HD + col);
#pragma unroll
        for (int q = 0; q < 16; q++)
            acc += w[i + q] * xv[q];
    }
    for (; i + 4 <= cnt; i += 4) {
        const float x0 = __ldg(xb + (size_t)idxs[i]     * HD + col);
        const float x1 = __ldg(xb + (size_t)idxs[i + 1] * HD + col);
        const float x2 = __ldg(xb + (size_t)idxs[i + 2] * HD + col);
        const float x3 = __ldg(xb + (size_t)idxs[i + 3] * HD + col);
        acc += w[i] * x0 + w[i + 1] * x1 + w[i + 2] * x2 + w[i + 3] * x3;
    }
    for (; i < cnt; i++)
        acc += w[i] * __ldg(xb + (size_t)idxs[i] * HD + col);

    out[(size_t)b * HD + col] = acc * inv;
}

// ---------------------------------------------------------------------------
extern "C" void kernel_launch(void* const* d_in, const int* in_sizes, int n_in,
                              void* d_out, int out_size)
{
    const float* x    = (const float*)d_in[0];   // [128,512,1024] f32
    const int*   mask = (const int*)  d_in[1];   // [128,512] int32
    const float* Wq   = (const float*)d_in[2];   // [512,1024] f32
    const float* bq   = (const float*)d_in[3];   // [512] f32
    const float* vq   = (const float*)d_in[4];   // [512] f32
    float* out = (float*)d_out;                  // [128,1024] f32

    cudaFuncSetAttribute(gemm_kernel, cudaFuncAttributeMaxDynamicSharedMemorySize, SMEM_GEMM);

    count_kernel<<<BS, SL>>>(mask);
    map_kernel<<<BS, SL>>>(mask);
    conv_kernel<<<CONV_GRID, 256>>>(x, Wq);
    gemm_kernel<<<dim3(NB, MAX_TILES), 256, SMEM_GEMM>>>(bq, vq);
    wsum_kernel<<<dim3(4, BS), 256>>>(x, out);
}